// round 9
// baseline (speedup 1.0000x reference)
#include <cuda_runtime.h>
#include <math.h>

// Fixed shapes for EpisodicMemory_57810259804539
#define BB 4
#define HH 16
#define SS 2048
#define DD 64
#define MM 1000
#define KK 10
#define HID (HH*DD)       // 1024
#define TT (SS+KK)        // 2058
#define EPSV 1e-8f

#define N0_4  (BB*SS*HID/4)          // 2,097,152  inputs as float4
#define NQ_4  N0_4                    // q as float4
#define NK_4  (BB*HH*TT*DD/4)         // 2,107,392  k_aug/v_aug as float4
#define HID4  (HID/4)                 // 256 float4 per memory row

#define SIMS_BLOCKS 500               // 8 warps each -> 4000 (b,m)
#define OUT4_TOTAL  (N0_4 + NQ_4 + 2*NK_4)          // 8,409,088
#define COPY_BLOCKS ((OUT4_TOTAL + 255) / 256)      // 32,848

// Scratch
__device__ float g_sims[BB*MM];

// ---------------------------------------------------------------------------
// K1: sims only. One warp per (b,m). Triggers PDL completion at entry so the
// downstream kernels launch underneath.
// ---------------------------------------------------------------------------
__global__ void __launch_bounds__(256) k1_sims(
    const float4* __restrict__ k4,
    const float4* __restrict__ mk4)
{
#if __CUDA_ARCH__ >= 900
    cudaTriggerProgrammaticLaunchCompletion();
#endif
    int tid = threadIdx.x;
    int wid = tid >> 5, lane = tid & 31;
    int wb = blockIdx.x * 8 + wid;            // 0..3999
    int b = wb / MM, m = wb % MM;

    const float4* row = mk4 + (size_t)m * HID4;
    // query_key[b][i] = k[b, i/64, S-1, i%64]; float4 chunks never cross h
    const float4* kb = k4 + ((b*HH)*SS + (SS-1))*16;

    float dot = 0.f, sq = 0.f;
    #pragma unroll
    for (int j = 0; j < 8; j++) {
        int i4 = lane + 32*j;                 // 0..255
        float4 r  = row[i4];
        float4 qv = kb[(i4 >> 4)*SS*16 + (i4 & 15)];
        dot += qv.x*r.x + qv.y*r.y + qv.z*r.z + qv.w*r.w;
        sq  += r.x*r.x + r.y*r.y + r.z*r.z + r.w*r.w;
    }
    #pragma unroll
    for (int off = 16; off; off >>= 1) {
        dot += __shfl_down_sync(0xffffffffu, dot, off);
        sq  += __shfl_down_sync(0xffffffffu, sq,  off);
    }
    if (lane == 0)
        g_sims[wb] = dot / (sqrtf(sq) + EPSV);
}

// ---------------------------------------------------------------------------
// K1b: 4 blocks (one per batch). Waits on K1 (grid dep sync), then:
//   top-10 (descending, lowest index on ties), gather t<K rows of k_aug/v_aug,
//   mask_aug, positions_k, seq_len_k scalar.
// Triggers its own PDL completion at entry so K2 starts immediately.
// ---------------------------------------------------------------------------
__global__ void __launch_bounds__(256) k1b_retrieval(
    const float4* __restrict__ mk4, const float4* __restrict__ mv4,
    const float*  __restrict__ attn_mask,
    const float*  __restrict__ mem_pos,
    float4* __restrict__ out4,
    float*  __restrict__ out,
    int off_mask, int off_pos, int off_seq, int has_scalar)
{
#if __CUDA_ARCH__ >= 900
    cudaTriggerProgrammaticLaunchCompletion();
    cudaGridDependencySynchronize();          // wait for K1's g_sims
#endif
    const int OFFK4 = N0_4 + NQ_4;            // k_aug start (float4)
    const int OFFV4 = OFFK4 + NK_4;           // v_aug start
    int tid = threadIdx.x;
    int b = blockIdx.x;

    __shared__ float ss[MM];
    __shared__ float rv[256];
    __shared__ int   ri[256];
    __shared__ int   top[KK];

    for (int i = tid; i < MM; i += 256)
        ss[i] = g_sims[b*MM + i];
    __syncthreads();

    // top-10: descending, lowest index on ties
    for (int j = 0; j < KK; j++) {
        float bv = -INFINITY; int bi = MM;
        for (int m = tid; m < MM; m += 256) {
            float vv = ss[m];
            if (vv > bv) { bv = vv; bi = m; }   // strict > => lowest idx wins
        }
        rv[tid] = bv; ri[tid] = bi;
        __syncthreads();
        for (int off = 128; off; off >>= 1) {
            if (tid < off) {
                float ov = rv[tid + off]; int oi = ri[tid + off];
                if (ov > rv[tid] || (ov == rv[tid] && oi < ri[tid])) {
                    rv[tid] = ov; ri[tid] = oi;
                }
            }
            __syncthreads();
        }
        if (tid == 0) { top[j] = ri[0]; ss[ri[0]] = -INFINITY; }
        __syncthreads();
    }

    // gather retrieved rows t<K of k_aug / v_aug (5120 float4)
    for (int e = tid; e < 2*KK*HID4; e += 256) {
        int which = e >= KK*HID4;
        int e2 = which ? e - KK*HID4 : e;
        int t  = e2 >> 8;
        int i4 = e2 & 255;
        int idx = top[t];
        float4 val = (which ? mv4 : mk4)[(size_t)idx*HID4 + i4];
        int dst = (which ? OFFV4 : OFFK4)
                + ((b*HH + (i4 >> 4))*TT + t)*16 + (i4 & 15);
        out4[dst] = val;
    }

    // mask_aug[b] = [ones(K), attention_mask[b]]
    for (int t = tid; t < TT; t += 256)
        out[off_mask + b*TT + t] =
            (t < KK) ? 1.0f : attn_mask[b*SS + (t - KK)];

    // positions_k[b] = [arange(S), mem_positions[top_idx[b]]]
    for (int t = tid; t < TT; t += 256)
        out[off_pos + b*TT + t] =
            (t < SS) ? (float)t : mem_pos[top[t - SS]];

    if (b == 0 && tid == 0 && has_scalar)
        out[off_seq] = (float)TT;
}

// ---------------------------------------------------------------------------
// K2: PURE copy, output-major, 1 float4/thread (R2-proven shape).
//     t<K rows of k_aug/v_aug are skipped (K1b owns them) so there is no
//     dependency on K1/K1b anywhere in this kernel.
// ---------------------------------------------------------------------------
__global__ void __launch_bounds__(256) k2_copy(
    const float4* __restrict__ inputs4, const float4* __restrict__ q4,
    const float4* __restrict__ k4, const float4* __restrict__ v4,
    float4* __restrict__ out4)
{
    int e = (int)blockIdx.x * 256 + threadIdx.x;
    if (e < N0_4) { out4[e] = inputs4[e]; return; }
    if (e < N0_4 + NQ_4) { out4[e] = q4[e - N0_4]; return; }
    int e2 = e - (N0_4 + NQ_4);
    if (e2 >= 2*NK_4) return;
    int which = e2 >= NK_4;
    int e3 = which ? e2 - NK_4 : e2;
    int d4 = e3 & 15;
    int r  = e3 >> 4;                     // bh*TT + t
    int t  = r % TT;
    int bh = r / TT;
    if (t < KK) return;                   // K1b owns these rows
    const float4* s = which ? v4 : k4;
    out4[e] = s[(bh*SS + (t - KK))*16 + d4];
}

// ---------------------------------------------------------------------------
extern "C" void kernel_launch(void* const* d_in, const int* in_sizes, int n_in,
                              void* d_out, int out_size)
{
    const float* inputs = (const float*)d_in[0];
    const float* q      = (const float*)d_in[1];
    const float* k      = (const float*)d_in[2];
    const float* v      = (const float*)d_in[3];
    const float* mask   = (const float*)d_in[4];
    const float* mk     = (const float*)d_in[5];
    const float* mv     = (const float*)d_in[6];
    const float* mpos   = (const float*)d_in[7];
    float* out = (float*)d_out;

    const int off_mask = OUT4_TOTAL * 4;                 // after the 4 big tensors
    const int off_tail = off_mask + BB * TT;
    // tuple order: inputs, q, k_aug, v_aug, mask_aug, seq_len_k, positions_k
    const int with_scalar = off_tail + 1 + BB * TT;
    int has_scalar = (out_size == with_scalar) ? 1 : 0;
    const int off_seq = off_tail;
    const int off_pos = off_tail + (has_scalar ? 1 : 0);

    // K1: sims (triggers PDL completion at entry)
    k1_sims<<<SIMS_BLOCKS, 256>>>((const float4*)k, (const float4*)mk);

    // K1b: retrieval, PDL-overlapped with K1 (grid-dep-syncs internally)
    {
        cudaLaunchConfig_t cfg = {};
        cfg.gridDim  = dim3(BB, 1, 1);
        cfg.blockDim = dim3(256, 1, 1);
        cfg.stream = 0;
        cudaLaunchAttribute attrs[1];
        attrs[0].id = cudaLaunchAttributeProgrammaticStreamSerialization;
        attrs[0].val.programmaticStreamSerializationAllowed = 1;
        cfg.attrs = attrs;
        cfg.numAttrs = 1;
        cudaLaunchKernelEx(&cfg, k1b_retrieval,
            (const float4*)mk, (const float4*)mv,
            mask, mpos,
            (float4*)out, out,
            off_mask, off_pos, off_seq, has_scalar);
    }

    // K2: pure copy, PDL-overlapped with K1b (no internal sync needed)
    {
        cudaLaunchConfig_t cfg = {};
        cfg.gridDim  = dim3(COPY_BLOCKS, 1, 1);
        cfg.blockDim = dim3(256, 1, 1);
        cfg.stream = 0;
        cudaLaunchAttribute attrs[1];
        attrs[0].id = cudaLaunchAttributeProgrammaticStreamSerialization;
        attrs[0].val.programmaticStreamSerializationAllowed = 1;
        cfg.attrs = attrs;
        cfg.numAttrs = 1;
        cudaLaunchKernelEx(&cfg, k2_copy,
            (const float4*)inputs, (const float4*)q,
            (const float4*)k, (const float4*)v,
            (float4*)out);
    }
}